// round 15
// baseline (speedup 1.0000x reference)
#include <cuda_runtime.h>
#include <cuda_bf16.h>
#include <cstdint>

// ---------------- problem constants ----------------
#define D_    768
#define H_    3072
#define E_    8
#define MAXPE 4096
#define NMAX  4096

#define BM 128
#define BN 128
#define BK 32

// uber-kernel segmentation
#define CV     64                       // cvt chunks per expert per weight tensor
#define G0PE   ((H_ / BN) * (MAXPE / BM))   // 24*32 = 768 GEMM0 CTAs / expert
#define G1PE   ((D_ / BN) * (MAXPE / BM))   // 6*32  = 192 GEMM1 CTAs / expert
#define S0END  (E_ * CV)                    // 512
#define S1END  (S0END + E_ * CV)            // 1024
#define S2END  (S1END + E_ * G0PE)          // 7168
#define S3END  (S2END + E_ * G1PE)          // 8704

typedef unsigned short u16;

// ---------------- device scratch (bf16 hi/lo planes) ----------------
__device__ u16   g_xhi[(size_t)NMAX * D_];
__device__ u16   g_xlo[(size_t)NMAX * D_];
__device__ u16   g_wfchi[(size_t)E_ * H_ * D_];
__device__ u16   g_wfclo[(size_t)E_ * H_ * D_];
__device__ u16   g_wprohi[(size_t)E_ * D_ * H_];
__device__ u16   g_wprolo[(size_t)E_ * D_ * H_];
__device__ u16   g_hhi[(size_t)E_ * MAXPE * H_];
__device__ u16   g_hlo[(size_t)E_ * MAXPE * H_];
__device__ int   g_tok[E_ * MAXPE];
__device__ float g_wt[E_ * MAXPE];
__device__ float g_probs[(size_t)NMAX * E_];
__device__ int   g_cnt[E_];
__device__ float g_sumprob[E_];
// dependency counters (uber kernel)
__device__ int   g_cvtfc[E_];
__device__ int   g_cvtpro[E_];
__device__ int   g_done0[E_];

// ---------------- helpers ----------------
__device__ __forceinline__ uint32_t smem_u32(const void* p) {
    uint32_t a;
    asm("{ .reg .u64 t; cvta.to.shared.u64 t, %1; cvt.u32.u64 %0, t; }" : "=r"(a) : "l"(p));
    return a;
}
__device__ __forceinline__ void ldsm4(uint32_t* r, uint32_t addr) {
    asm volatile("ldmatrix.sync.aligned.m8n8.x4.shared.b16 {%0,%1,%2,%3}, [%4];"
                 : "=r"(r[0]), "=r"(r[1]), "=r"(r[2]), "=r"(r[3]) : "r"(addr));
}
__device__ __forceinline__ void mma_bf16(float* c, const uint32_t* a, uint32_t b0, uint32_t b1) {
    asm volatile("mma.sync.aligned.m16n8k16.row.col.f32.bf16.bf16.f32 "
                 "{%0,%1,%2,%3}, {%4,%5,%6,%7}, {%8,%9}, {%0,%1,%2,%3};"
                 : "+f"(c[0]), "+f"(c[1]), "+f"(c[2]), "+f"(c[3])
                 : "r"(a[0]), "r"(a[1]), "r"(a[2]), "r"(a[3]), "r"(b0), "r"(b1));
}
__device__ __forceinline__ void cpa16(uint32_t dst, const void* src) {
    asm volatile("cp.async.cg.shared.global [%0], [%1], 16;" :: "r"(dst), "l"(src));
}
__device__ __forceinline__ void cp_commit() {
    asm volatile("cp.async.commit_group;" ::: "memory");
}
__device__ __forceinline__ void cp_wait1() {
    asm volatile("cp.async.wait_group 1;" ::: "memory");
}
// split two floats -> hi bf16x2 (packed) and lo bf16x2 (packed)
__device__ __forceinline__ void split2(float x, float y, uint32_t& h, uint32_t& l) {
    __nv_bfloat162 a = __floats2bfloat162_rn(x, y);
    h = *reinterpret_cast<uint32_t*>(&a);
    float f0 = __uint_as_float(h << 16);
    float f1 = __uint_as_float(h & 0xffff0000u);
    __nv_bfloat162 b = __floats2bfloat162_rn(x - f0, y - f1);
    l = *reinterpret_cast<uint32_t*>(&b);
}

// ---------------- dependency counters ----------------
__device__ __forceinline__ void signal_cnt(int* p) {
    __syncthreads();
    __threadfence();
    if (threadIdx.x == 0) atomicAdd(p, 1);
}
__device__ __forceinline__ void wait_cnt(int* p, int target) {
    if (threadIdx.x == 0) {
        while (atomicAdd(p, 0) < target) __nanosleep(64);
    }
    __syncthreads();
    __threadfence();
}

// ---------------- kernel: fp32 -> bf16 hi/lo planes (standalone, for x) ----------
__global__ void cvt_kernel(const float* __restrict__ src, u16* __restrict__ hi,
                           u16* __restrict__ lo, int n4) {
    for (int i = blockIdx.x * blockDim.x + threadIdx.x; i < n4;
         i += gridDim.x * blockDim.x) {
        float4 v = ((const float4*)src)[i];
        uint32_t h0, h1, l0, l1;
        split2(v.x, v.y, h0, l0);
        split2(v.z, v.w, h1, l1);
        ((uint2*)hi)[i] = make_uint2(h0, h1);
        ((uint2*)lo)[i] = make_uint2(l0, l1);
    }
}

// ---------------- kernel 0: zero output + counters ----------------
__global__ void zero_kernel(float* __restrict__ out, int out_size) {
    for (int i = blockIdx.x * blockDim.x + threadIdx.x; i < out_size;
         i += gridDim.x * blockDim.x)
        out[i] = 0.0f;
    if (blockIdx.x == 0 && threadIdx.x < E_) {
        g_cnt[threadIdx.x]    = 0;
        g_cvtfc[threadIdx.x]  = 0;
        g_cvtpro[threadIdx.x] = 0;
        g_done0[threadIdx.x]  = 0;
    }
}

// ---------------- kernel 1: gating ----------------
__global__ __launch_bounds__(256) void gate_kernel(const float* __restrict__ x,
                                                   const float* __restrict__ gw,
                                                   int N) {
    int token = blockIdx.x * 8 + (threadIdx.x >> 5);
    int lane  = threadIdx.x & 31;
    if (token >= N) return;

    const float* xr = x + (size_t)token * D_;
    float xs[D_ / 32];
#pragma unroll
    for (int i = 0; i < D_ / 32; i++) xs[i] = xr[lane + i * 32];

    float p[E_];
#pragma unroll
    for (int e = 0; e < E_; e++) {
        const float* g = gw + e * D_;
        float s = 0.0f;
#pragma unroll
        for (int i = 0; i < D_ / 32; i++) s += xs[i] * g[lane + i * 32];
#pragma unroll
        for (int o = 16; o; o >>= 1) s += __shfl_xor_sync(0xffffffffu, s, o);
        p[e] = s;
    }

    if (lane == 0) {
        float mx = p[0];
#pragma unroll
        for (int e = 1; e < E_; e++) mx = fmaxf(mx, p[e]);
        float sum = 0.0f;
#pragma unroll
        for (int e = 0; e < E_; e++) { p[e] = expf(p[e] - mx); sum += p[e]; }
        float inv = 1.0f / sum;
#pragma unroll
        for (int e = 0; e < E_; e++) {
            p[e] *= inv;
            g_probs[(size_t)token * E_ + e] = p[e];
        }
        int i1 = 0;
#pragma unroll
        for (int e = 1; e < E_; e++) if (p[e] > p[i1]) i1 = e;
        int i2 = (i1 == 0) ? 1 : 0;
#pragma unroll
        for (int e = 0; e < E_; e++) if (e != i1 && p[e] > p[i2]) i2 = e;
        float s2 = p[i1] + p[i2];
        float w1 = p[i1] / s2, w2 = p[i2] / s2;

        int pos = atomicAdd(&g_cnt[i1], 1);
        g_tok[i1 * MAXPE + pos] = token; g_wt[i1 * MAXPE + pos] = w1;
        pos = atomicAdd(&g_cnt[i2], 1);
        g_tok[i2 * MAXPE + pos] = token; g_wt[i2 * MAXPE + pos] = w2;
    }
}

// ---------------- kernel 2: deterministic column-sum of probs ----------------
__global__ void reduce_probs_kernel(int N) {
    __shared__ float sm[256];
    int e = blockIdx.x;
    float s = 0.0f;
    for (int i = threadIdx.x; i < N; i += 256) s += g_probs[(size_t)i * E_ + e];
    sm[threadIdx.x] = s;
    __syncthreads();
    for (int o = 128; o; o >>= 1) {
        if (threadIdx.x < o) sm[threadIdx.x] += sm[threadIdx.x + o];
        __syncthreads();
    }
    if (threadIdx.x == 0) g_sumprob[e] = sm[0];
}

// ---------------- GEMM body: mma.sync bf16x3, cp.async 3-stage ----------------
// Block tile 128x128x32; warp grid 2x4, warp tile 64x32; 64 accumulators.
// Stage (32KB): A_hi[128 rows x 64B] @0, A_lo @8192, B_hi @16384, B_lo @24576.
// Chunk c of row r stored at 16B slot (c ^ ((r>>1)&3)) -> conflict-free.
// MODE 0: h = relu(x_planes @ wfc_planes^T)^2 -> g_h hi/lo planes (Kdim = D_)
// MODE 1: out += wt * (g_h planes @ wproj planes^T)  (atomicAdd) (Kdim = H_)
#define STAGE_BYTES 32768u
#define NSTAGE      3
#define SMEM_TOTAL  (NSTAGE * STAGE_BYTES)

template <int MODE>
__device__ __forceinline__ void gemm_body(const u16* __restrict__ Ahi,
                                          const u16* __restrict__ Alo,
                                          const u16* __restrict__ Bhi,
                                          const u16* __restrict__ Blo,
                                          float* __restrict__ out, int Kdim, int e,
                                          int m0, int n0, int cnt, uint32_t sb) {
    const int tid  = threadIdx.x;
    const int warp = tid >> 5, lane = tid & 31;
    const int wm = warp >> 2, wn = warp & 3;  // 2 x 4 warp grid, warp tile 64x32

    // ---- loader mapping: 2 threads per row, 2 chunks of 16B each plane ----
    const int lrow  = tid >> 1;
    const int lhalf = tid & 1;
    const u16 *a_hi, *a_lo;
    if (MODE == 0) {
        int m   = m0 + lrow;
        int tok = g_tok[e * MAXPE + ((m < cnt) ? m : m0)];
        a_hi = Ahi + (size_t)tok * D_ + lhalf * 16;
        a_lo = Alo + (size_t)tok * D_ + lhalf * 16;
    } else {
        size_t off = ((size_t)(e * MAXPE + m0 + lrow)) * H_ + lhalf * 16;
        a_hi = Ahi + off;
        a_lo = Alo + off;
    }
    const size_t boff = (size_t)e * ((size_t)H_ * D_) + (size_t)(n0 + lrow) * Kdim +
                        (size_t)(lhalf * 16);
    const u16* b_hi = Bhi + boff;
    const u16* b_lo = Blo + boff;

    // swizzled dst offsets for the 2 chunks (c = lhalf*2, lhalf*2+1)
    const uint32_t lsw   = (uint32_t)((lrow >> 1) & 3);
    const uint32_t st_c0 = (uint32_t)lrow * 64u + (((uint32_t)(lhalf * 2) ^ lsw) * 16u);
    const uint32_t st_c1 = (uint32_t)lrow * 64u + (((uint32_t)(lhalf * 2 + 1) ^ lsw) * 16u);

    // ---- ldmatrix per-lane swizzled addressing ----
    const int      row_a = wm * 64 + (lane & 15);
    const uint32_t sw_a  = (uint32_t)((row_a >> 1) & 3);
    const uint32_t a_row = (uint32_t)row_a * 64u;
    const uint32_t ca    = (uint32_t)(lane >> 4);
    const int      row_b = wn * 32 + ((lane >> 4) & 1) * 8 + (lane & 7);
    const uint32_t sw_b  = (uint32_t)((row_b >> 1) & 3);
    const uint32_t b_row = (uint32_t)row_b * 64u;
    const uint32_t cb    = (uint32_t)((lane >> 3) & 1);

    float acc[64];
#pragma unroll
    for (int i = 0; i < 64; i++) acc[i] = 0.0f;

    const int nk = Kdim / BK;

    // stage loader: 8 x cp.async(16B) per thread
    auto load_stage = [&](int kt, int slot) {
        const uint32_t base = sb + (uint32_t)slot * STAGE_BYTES;
        const int koff = kt * BK;
        cpa16(base + st_c0, a_hi + koff);
        cpa16(base + st_c1, a_hi + koff + 8);
        cpa16(base + 8192 + st_c0, a_lo + koff);
        cpa16(base + 8192 + st_c1, a_lo + koff + 8);
        cpa16(base + 16384 + st_c0, b_hi + koff);
        cpa16(base + 16384 + st_c1, b_hi + koff + 8);
        cpa16(base + 24576 + st_c0, b_lo + koff);
        cpa16(base + 24576 + st_c1, b_lo + koff + 8);
    };

    // prologue: fill stages 0 and 1
    load_stage(0, 0);
    cp_commit();
    if (nk > 1) load_stage(1, 1);
    cp_commit();

    int slot = 0;
    for (int kt = 0; kt < nk; ++kt) {
        cp_wait1();
        __syncthreads();
        if (kt + 2 < nk) {
            int s2 = slot + 2;
            if (s2 >= NSTAGE) s2 -= NSTAGE;
            load_stage(kt + 2, s2);
        }
        cp_commit();

        const uint32_t base = sb + (uint32_t)slot * STAGE_BYTES;
#pragma unroll
        for (int ks = 0; ks < 2; ks++) {
            uint32_t ah[4][4], al[4][4];
            const uint32_t aoff = base + a_row + ((((uint32_t)(ks * 2) + ca) ^ sw_a) * 16u);
            const uint32_t boff2 =
                base + 16384 + b_row + ((((uint32_t)(ks * 2) + cb) ^ sw_b) * 16u);
#pragma unroll
            for (int am = 0; am < 4; am++) {
                ldsm4(ah[am], aoff + am * 1024);
                ldsm4(al[am], aoff + 8192 + am * 1024);
            }
#pragma unroll
            for (int g = 0; g < 2; g++) {
                uint32_t bh[4], bl[4];
                ldsm4(bh, boff2 + g * 1024);
                ldsm4(bl, boff2 + 8192 + g * 1024);
#pragma unroll
                for (int am = 0; am < 4; am++) {
                    float* c0 = &acc[(am * 4 + g * 2) * 4];
                    float* c1 = &acc[(am * 4 + g * 2 + 1) * 4];
                    mma_bf16(c0, ah[am], bh[0], bh[1]);
                    mma_bf16(c1, ah[am], bh[2], bh[3]);
                    mma_bf16(c0, ah[am], bl[0], bl[1]);
                    mma_bf16(c1, ah[am], bl[2], bl[3]);
                    mma_bf16(c0, al[am], bh[0], bh[1]);
                    mma_bf16(c1, al[am], bh[2], bh[3]);
                }
            }
        }
        slot = (slot + 1 == NSTAGE) ? 0 : slot + 1;
    }

    // ---- epilogue ----
    const int qr = lane >> 2;            // row within 8
    const int qc = (lane & 3) * 2;       // col pair within 8
    if (MODE == 0) {
#pragma unroll
        for (int am = 0; am < 4; am++)
#pragma unroll
            for (int hh = 0; hh < 2; hh++) {
                const int m = m0 + wm * 64 + am * 16 + qr + hh * 8;
                if (m >= cnt) continue;
                const size_t rowoff =
                    ((size_t)(e * MAXPE + m)) * H_ + n0 + wn * 32;
#pragma unroll
                for (int an = 0; an < 4; an++) {
                    const float* c = &acc[(am * 4 + an) * 4 + hh * 2];
                    float t0 = fmaxf(c[0], 0.f), t1 = fmaxf(c[1], 0.f);
                    float v0 = t0 * t0, v1 = t1 * t1;
                    uint32_t h, l;
                    split2(v0, v1, h, l);
                    const size_t off = rowoff + an * 8 + qc;
                    *(uint32_t*)(g_hhi + off) = h;
                    *(uint32_t*)(g_hlo + off) = l;
                }
            }
    } else {
#pragma unroll
        for (int am = 0; am < 4; am++)
#pragma unroll
            for (int hh = 0; hh < 2; hh++) {
                const int m = m0 + wm * 64 + am * 16 + qr + hh * 8;
                if (m >= cnt) continue;
                const int tok = g_tok[e * MAXPE + m];
                const float wt = g_wt[e * MAXPE + m];
                float* orow = out + (size_t)tok * D_ + n0 + wn * 32;
#pragma unroll
                for (int an = 0; an < 4; an++) {
                    const float* c = &acc[(am * 4 + an) * 4 + hh * 2];
                    atomicAdd(orow + an * 8 + qc, wt * c[0]);
                    atomicAdd(orow + an * 8 + qc + 1, wt * c[1]);
                }
            }
    }
}

// ---------------- uber kernel: cvt(wfc) | cvt(wproj) | GEMM0 | GEMM1 ----------
// Linear blockIdx segments with forward-only spin-wait dependencies:
//   s0 [0, S0END):       cvt w_fc   chunk (expert e = idx/CV)   -> signal g_cvtfc[e]
//   s1 [S0END, S1END):   cvt w_proj chunk                       -> signal g_cvtpro[e]
//   s2 [S1END, S2END):   GEMM0(e) waits g_cvtfc[e]==CV          -> signal g_done0[e]
//   s3 [S2END, S3END):   GEMM1(e) waits g_done0[e]==G0PE && g_cvtpro[e]==CV
// All waits target strictly earlier blocks; dispatcher issues blocks in order.
__global__ __launch_bounds__(256, 2) void moe_uber(
    const float* __restrict__ wfc, const float* __restrict__ wproj,
    const u16* __restrict__ xhi, const u16* __restrict__ xlo,
    u16* __restrict__ wfchi, u16* __restrict__ wfclo,
    u16* __restrict__ wprohi, u16* __restrict__ wprolo,
    const u16* __restrict__ hhi, const u16* __restrict__ hlo,
    float* __restrict__ out) {
    extern __shared__ __align__(128) char smem[];
    const uint32_t sb  = smem_u32(smem);
    const int      bid = blockIdx.x;
    const size_t   WSZ = (size_t)H_ * D_;
    const int      C4  = (int)(WSZ / 4 / CV);  // float4 per cvt chunk

    if (bid < S1END) {
        // ---- cvt segments ----
        const bool fc  = (bid < S0END);
        const int  idx = fc ? bid : bid - S0END;
        const int  e   = idx / CV, ch = idx % CV;
        const size_t off4 = (size_t)e * (WSZ / 4) + (size_t)ch * C4;
        const float4* src = (const float4*)(fc ? wfc : wproj) + off4;
        uint2* hi = (uint2*)(fc ? wfchi : wprohi) + off4;
        uint2* lo = (uint2*)(fc ? wfclo : wprolo) + off4;
        for (int i = threadIdx.x; i < C4; i += 256) {
            float4 v = src[i];
            uint32_t h0, h1, l0, l1;
            split2(v.x, v.y, h0, l0);
            split2(v.z, v.w, h1, l1);
            hi[i] = make_uint2(h0, h1);
            lo[i] = make_uint2(l0, l1);
        }
        signal_cnt(fc ? &g_cvtfc[e] : &g_cvtpro[e]);
    } else if (bid < S2END) {
        // ---- GEMM0 ----
        const int idx = bid - S1END;
        const int e   = idx / G0PE, t = idx % G0PE;
        const int nt  = t % (H_ / BN), mt = t / (H_ / BN);
        wait_cnt(&g_cvtfc[e], CV);
        const int cnt = g_cnt[e];
        const int m0  = mt * BM;
        if (m0 < cnt)
            gemm_body<0>(xhi, xlo, wfchi, wfclo, nullptr, D_, e, m0, nt * BN, cnt, sb);
        signal_cnt(&g_done0[e]);
    } else {
        // ---- GEMM1 ----
        const int idx = bid - S2END;
        const int e   = idx / G1PE, t = idx % G1PE;
        const int nt  = t % (D_ / BN), mt = t / (D_ / BN);
        wait_cnt(&g_done0[e], G0PE);
        wait_cnt(&g_cvtpro[e], CV);
        const int cnt = g_cnt[e];
        const int m0  = mt * BM;
        if (m0 < cnt)
            gemm_body<1>(hhi, hlo, wprohi, wprolo, out, H_, e, m0, nt * BN, cnt, sb);
    }
}

// ---------------- loss ----------------
__global__ void loss_kernel(float* __restrict__ out, int N, int out_size) {
    if (out_size <= N * D_) return;
    float loss = 0.0f;
    for (int e = 0; e < E_; e++)
        loss += (g_sumprob[e] / (float)N) * ((float)g_cnt[e] / (float)N);
    out[(size_t)N * D_] = loss * (float)E_;
}

// ---------------- launch ----------------
extern "C" void kernel_launch(void* const* d_in, const int* in_sizes, int n_in,
                              void* d_out, int out_size) {
    const float* x     = (const float*)d_in[0];
    const float* gw    = (const float*)d_in[1];
    const float* wfc   = (const float*)d_in[2];
    const float* wproj = (const float*)d_in[3];
    float* out = (float*)d_out;
    int N = in_sizes[0] / D_;  // 4096

    cudaFuncSetAttribute(moe_uber, cudaFuncAttributeMaxDynamicSharedMemorySize, SMEM_TOTAL);

    // resolve device-global plane addresses (host-side)
    u16 *xhi, *xlo, *wfchi, *wfclo, *wprohi, *wprolo, *hhi, *hlo;
    cudaGetSymbolAddress((void**)&xhi, g_xhi);
    cudaGetSymbolAddress((void**)&xlo, g_xlo);
    cudaGetSymbolAddress((void**)&wfchi, g_wfchi);
    cudaGetSymbolAddress((void**)&wfclo, g_wfclo);
    cudaGetSymbolAddress((void**)&wprohi, g_wprohi);
    cudaGetSymbolAddress((void**)&wprolo, g_wprolo);
    cudaGetSymbolAddress((void**)&hhi, g_hhi);
    cudaGetSymbolAddress((void**)&hlo, g_hlo);

    zero_kernel<<<1024, 256>>>(out, out_size);
    cvt_kernel<<<256, 256>>>(x, xhi, xlo, N * D_ / 4);
    gate_kernel<<<(N + 7) / 8, 256>>>(x, gw, N);
    reduce_probs_kernel<<<E_, 256>>>(N);

    moe_uber<<<S3END, 256, SMEM_TOTAL>>>(wfc, wproj, xhi, xlo, wfchi, wfclo,
                                         wprohi, wprolo, hhi, hlo, out);

    loss_kernel<<<1, 1>>>(out, N, out_size);
}

// round 16
// speedup vs baseline: 1.0173x; 1.0173x over previous
#include <cuda_runtime.h>
#include <cuda_bf16.h>
#include <cstdint>

// ---------------- problem constants ----------------
#define D_    768
#define H_    3072
#define E_    8
#define MAXPE 4096
#define NMAX  4096

#define BM 128
#define BN 128
#define BK 32

#define SPLITK 3
#define KLEN   (H_ / SPLITK)   // 1024

typedef unsigned short u16;

// ---------------- device scratch ----------------
__device__ u16   g_xhi[(size_t)NMAX * D_];
__device__ u16   g_xlo[(size_t)NMAX * D_];
__device__ u16   g_wfchi[(size_t)E_ * H_ * D_];
__device__ u16   g_wfclo[(size_t)E_ * H_ * D_];
__device__ u16   g_wprohi[(size_t)E_ * D_ * H_];
__device__ u16   g_wprolo[(size_t)E_ * D_ * H_];
__device__ u16   g_hhi[(size_t)E_ * MAXPE * H_];
__device__ u16   g_hlo[(size_t)E_ * MAXPE * H_];
__device__ float g_y[(size_t)SPLITK * E_ * MAXPE * D_];   // GEMM1 partials
__device__ int   g_tok[E_ * MAXPE];
__device__ float g_wt[E_ * MAXPE];
__device__ int   g_a1[NMAX];
__device__ int   g_a2[NMAX];
__device__ float g_probs[(size_t)NMAX * E_];
__device__ int   g_cnt[E_];
__device__ float g_sumprob[E_];

// ---------------- helpers ----------------
__device__ __forceinline__ uint32_t smem_u32(const void* p) {
    uint32_t a;
    asm("{ .reg .u64 t; cvta.to.shared.u64 t, %1; cvt.u32.u64 %0, t; }" : "=r"(a) : "l"(p));
    return a;
}
__device__ __forceinline__ void ldsm4(uint32_t* r, uint32_t addr) {
    asm volatile("ldmatrix.sync.aligned.m8n8.x4.shared.b16 {%0,%1,%2,%3}, [%4];"
                 : "=r"(r[0]), "=r"(r[1]), "=r"(r[2]), "=r"(r[3]) : "r"(addr));
}
__device__ __forceinline__ void mma_bf16(float* c, const uint32_t* a, uint32_t b0, uint32_t b1) {
    asm volatile("mma.sync.aligned.m16n8k16.row.col.f32.bf16.bf16.f32 "
                 "{%0,%1,%2,%3}, {%4,%5,%6,%7}, {%8,%9}, {%0,%1,%2,%3};"
                 : "+f"(c[0]), "+f"(c[1]), "+f"(c[2]), "+f"(c[3])
                 : "r"(a[0]), "r"(a[1]), "r"(a[2]), "r"(a[3]), "r"(b0), "r"(b1));
}
__device__ __forceinline__ void cpa16(uint32_t dst, const void* src) {
    asm volatile("cp.async.cg.shared.global [%0], [%1], 16;" :: "r"(dst), "l"(src));
}
__device__ __forceinline__ void cp_commit() {
    asm volatile("cp.async.commit_group;" ::: "memory");
}
__device__ __forceinline__ void cp_wait1() {
    asm volatile("cp.async.wait_group 1;" ::: "memory");
}
// split two floats -> hi bf16x2 (packed) and lo bf16x2 (packed)
__device__ __forceinline__ void split2(float x, float y, uint32_t& h, uint32_t& l) {
    __nv_bfloat162 a = __floats2bfloat162_rn(x, y);
    h = *reinterpret_cast<uint32_t*>(&a);
    float f0 = __uint_as_float(h << 16);
    float f1 = __uint_as_float(h & 0xffff0000u);
    __nv_bfloat162 b = __floats2bfloat162_rn(x - f0, y - f1);
    l = *reinterpret_cast<uint32_t*>(&b);
}

// ---------------- kernel: fused fp32 -> bf16 hi/lo planes (x, wfc, wproj) ------
#define X4  (NMAX * D_ / 4)
#define W4  (E_ * H_ * D_ / 4)
__global__ void cvt3_kernel(const float* __restrict__ x, const float* __restrict__ wfc,
                            const float* __restrict__ wproj) {
    const int total = X4 + 2 * W4;
    for (int i = blockIdx.x * blockDim.x + threadIdx.x; i < total;
         i += gridDim.x * blockDim.x) {
        const float4* src;
        uint2 *hi, *lo;
        int j;
        if (i < X4) {
            j = i; src = (const float4*)x;
            hi = (uint2*)g_xhi; lo = (uint2*)g_xlo;
        } else if (i < X4 + W4) {
            j = i - X4; src = (const float4*)wfc;
            hi = (uint2*)g_wfchi; lo = (uint2*)g_wfclo;
        } else {
            j = i - X4 - W4; src = (const float4*)wproj;
            hi = (uint2*)g_wprohi; lo = (uint2*)g_wprolo;
        }
        float4 v = src[j];
        uint32_t h0, h1, l0, l1;
        split2(v.x, v.y, h0, l0);
        split2(v.z, v.w, h1, l1);
        hi[j] = make_uint2(h0, h1);
        lo[j] = make_uint2(l0, l1);
    }
}

// ---------------- kernel 0: init counters (+ tail of out beyond loss slot) -----
__global__ void zero_kernel(float* __restrict__ out, int out_size, int N) {
    int tail = N * D_ + 1;
    for (int i = tail + blockIdx.x * blockDim.x + threadIdx.x; i < out_size;
         i += gridDim.x * blockDim.x)
        out[i] = 0.0f;
    if (blockIdx.x == 0 && threadIdx.x < E_) g_cnt[threadIdx.x] = 0;
}

// ---------------- kernel 1: gating ----------------
__global__ __launch_bounds__(256) void gate_kernel(const float* __restrict__ x,
                                                   const float* __restrict__ gw,
                                                   int N) {
    int token = blockIdx.x * 8 + (threadIdx.x >> 5);
    int lane  = threadIdx.x & 31;
    if (token >= N) return;

    const float* xr = x + (size_t)token * D_;
    float xs[D_ / 32];
#pragma unroll
    for (int i = 0; i < D_ / 32; i++) xs[i] = xr[lane + i * 32];

    float p[E_];
#pragma unroll
    for (int e = 0; e < E_; e++) {
        const float* g = gw + e * D_;
        float s = 0.0f;
#pragma unroll
        for (int i = 0; i < D_ / 32; i++) s += xs[i] * g[lane + i * 32];
#pragma unroll
        for (int o = 16; o; o >>= 1) s += __shfl_xor_sync(0xffffffffu, s, o);
        p[e] = s;
    }

    if (lane == 0) {
        float mx = p[0];
#pragma unroll
        for (int e = 1; e < E_; e++) mx = fmaxf(mx, p[e]);
        float sum = 0.0f;
#pragma unroll
        for (int e = 0; e < E_; e++) { p[e] = expf(p[e] - mx); sum += p[e]; }
        float inv = 1.0f / sum;
#pragma unroll
        for (int e = 0; e < E_; e++) {
            p[e] *= inv;
            g_probs[(size_t)token * E_ + e] = p[e];
        }
        int i1 = 0;
#pragma unroll
        for (int e = 1; e < E_; e++) if (p[e] > p[i1]) i1 = e;
        int i2 = (i1 == 0) ? 1 : 0;
#pragma unroll
        for (int e = 0; e < E_; e++) if (e != i1 && p[e] > p[i2]) i2 = e;
        float s2 = p[i1] + p[i2];
        float w1 = p[i1] / s2, w2 = p[i2] / s2;

        int pos = atomicAdd(&g_cnt[i1], 1);
        g_tok[i1 * MAXPE + pos] = token; g_wt[i1 * MAXPE + pos] = w1;
        g_a1[token] = i1 * MAXPE + pos;
        pos = atomicAdd(&g_cnt[i2], 1);
        g_tok[i2 * MAXPE + pos] = token; g_wt[i2 * MAXPE + pos] = w2;
        g_a2[token] = i2 * MAXPE + pos;
    }
}

// ---------------- kernel 2: deterministic column-sum of probs ----------------
__global__ void reduce_probs_kernel(int N) {
    __shared__ float sm[256];
    int e = blockIdx.x;
    float s = 0.0f;
    for (int i = threadIdx.x; i < N; i += 256) s += g_probs[(size_t)i * E_ + e];
    sm[threadIdx.x] = s;
    __syncthreads();
    for (int o = 128; o; o >>= 1) {
        if (threadIdx.x < o) sm[threadIdx.x] += sm[threadIdx.x + o];
        __syncthreads();
    }
    if (threadIdx.x == 0) g_sumprob[e] = sm[0];
}

// ---------------- grouped GEMM: mma.sync bf16x3, cp.async 3-stage, 2 CTA/SM ----
// Block tile 128x128x32; warp grid 2x4, warp tile 64x32; 64 accumulators.
// __launch_bounds__(256, 2): regs<=128 -> 2 CTAs/SM (2x96KB smem = 192KB).
// Stage (32KB): A_hi[128 rows x 64B] @0, A_lo @8192, B_hi @16384, B_lo @24576.
// Chunk c of row r stored at 16B slot (c ^ ((r>>1)&3)) -> conflict-free.
// MODE 0: h = relu(x_planes @ wfc_planes^T)^2 -> g_h hi/lo planes (K = D_)
// MODE 1: split-K partial: g_y[part] = g_h planes @ wproj planes^T over KLEN
#define STAGE_BYTES 32768u
#define NSTAGE      3
#define SMEM_TOTAL  (NSTAGE * STAGE_BYTES)

template <int MODE>
__global__ __launch_bounds__(256, 2) void moe_gemm_mma(const u16* __restrict__ Ahi,
                                                       const u16* __restrict__ Alo,
                                                       const u16* __restrict__ Bhi,
                                                       const u16* __restrict__ Blo,
                                                       int Kdim) {
    const int e    = (MODE == 0) ? blockIdx.z : (blockIdx.z / SPLITK);
    const int part = (MODE == 0) ? 0 : (blockIdx.z % SPLITK);
    const int kbeg = part * KLEN;
    const int klen = (MODE == 0) ? D_ : KLEN;

    const int cnt = g_cnt[e];
    const int m0  = blockIdx.y * BM;
    if (m0 >= cnt) return;
    const int n0 = blockIdx.x * BN;

    extern __shared__ __align__(128) char smem[];
    const uint32_t sb = smem_u32(smem);

    const int tid  = threadIdx.x;
    const int warp = tid >> 5, lane = tid & 31;
    const int wm = warp >> 2, wn = warp & 3;  // 2 x 4 warp grid, warp tile 64x32

    // ---- loader mapping: 2 threads per row, 2 chunks of 16B each plane ----
    const int lrow  = tid >> 1;
    const int lhalf = tid & 1;
    const u16 *a_hi, *a_lo;
    if (MODE == 0) {
        int m   = m0 + lrow;
        int tok = g_tok[e * MAXPE + ((m < cnt) ? m : m0)];
        a_hi = Ahi + (size_t)tok * D_ + lhalf * 16;
        a_lo = Alo + (size_t)tok * D_ + lhalf * 16;
    } else {
        size_t off = ((size_t)(e * MAXPE + m0 + lrow)) * H_ + lhalf * 16;
        a_hi = Ahi + off;
        a_lo = Alo + off;
    }
    const size_t boff = (size_t)e * ((size_t)H_ * D_) + (size_t)(n0 + lrow) * Kdim +
                        (size_t)(lhalf * 16);
    const u16* b_hi = Bhi + boff;
    const u16* b_lo = Blo + boff;

    // swizzled dst offsets for the 2 chunks (c = lhalf*2, lhalf*2+1)
    const uint32_t lsw   = (uint32_t)((lrow >> 1) & 3);
    const uint32_t st_c0 = (uint32_t)lrow * 64u + (((uint32_t)(lhalf * 2) ^ lsw) * 16u);
    const uint32_t st_c1 = (uint32_t)lrow * 64u + (((uint32_t)(lhalf * 2 + 1) ^ lsw) * 16u);

    // ---- ldmatrix per-lane swizzled addressing ----
    const int      row_a = wm * 64 + (lane & 15);
    const uint32_t sw_a  = (uint32_t)((row_a >> 1) & 3);
    const uint32_t a_row = (uint32_t)row_a * 64u;
    const uint32_t ca    = (uint32_t)(lane >> 4);
    const int      row_b = wn * 32 + ((lane >> 4) & 1) * 8 + (lane & 7);
    const uint32_t sw_b  = (uint32_t)((row_b >> 1) & 3);
    const uint32_t b_row = (uint32_t)row_b * 64u;
    const uint32_t cb    = (uint32_t)((lane >> 3) & 1);

    float acc[64];
#pragma unroll
    for (int i = 0; i < 64; i++) acc[i] = 0.0f;

    const int nk = klen / BK;

    // stage loader: 8 x cp.async(16B) per thread
    auto load_stage = [&](int kt, int slot) {
        const uint32_t base = sb + (uint32_t)slot * STAGE_BYTES;
        const int koff = kbeg + kt * BK;
        cpa16(base + st_c0, a_hi + koff);
        cpa16(base + st_c1, a_hi + koff + 8);
        cpa16(base + 8192 + st_c0, a_lo + koff);
        cpa16(base + 8192 + st_c1, a_lo + koff + 8);
        cpa16(base + 16384 + st_c0, b_hi + koff);
        cpa16(base + 16384 + st_c1, b_hi + koff + 8);
        cpa16(base + 24576 + st_c0, b_lo + koff);
        cpa16(base + 24576 + st_c1, b_lo + koff + 8);
    };

    // prologue: fill stages 0 and 1
    load_stage(0, 0);
    cp_commit();
    if (nk > 1) load_stage(1, 1);
    cp_commit();

    int slot = 0;
    for (int kt = 0; kt < nk; ++kt) {
        cp_wait1();
        __syncthreads();
        if (kt + 2 < nk) {
            int s2 = slot + 2;
            if (s2 >= NSTAGE) s2 -= NSTAGE;
            load_stage(kt + 2, s2);
        }
        cp_commit();

        const uint32_t base = sb + (uint32_t)slot * STAGE_BYTES;
#pragma unroll
        for (int ks = 0; ks < 2; ks++) {
            uint32_t ah[4][4], al[4][4];
            const uint32_t aoff = base + a_row + ((((uint32_t)(ks * 2) + ca) ^ sw_a) * 16u);
            const uint32_t boff2 =
                base + 16384 + b_row + ((((uint32_t)(ks * 2) + cb) ^ sw_b) * 16u);
#pragma unroll
            for (int am = 0; am < 4; am++) {
                ldsm4(ah[am], aoff + am * 1024);
                ldsm4(al[am], aoff + 8192 + am * 1024);
            }
#pragma unroll
            for (int g = 0; g < 2; g++) {
                uint32_t bh[4], bl[4];
                ldsm4(bh, boff2 + g * 1024);
                ldsm4(bl, boff2 + 8192 + g * 1024);
#pragma unroll
                for (int am = 0; am < 4; am++) {
                    float* c0 = &acc[(am * 4 + g * 2) * 4];
                    float* c1 = &acc[(am * 4 + g * 2 + 1) * 4];
                    mma_bf16(c0, ah[am], bh[0], bh[1]);
                    mma_bf16(c1, ah[am], bh[2], bh[3]);
                    mma_bf16(c0, ah[am], bl[0], bl[1]);
                    mma_bf16(c1, ah[am], bl[2], bl[3]);
                    mma_bf16(c0, al[am], bh[0], bh[1]);
                    mma_bf16(c1, al[am], bh[2], bh[3]);
                }
            }
        }
        slot = (slot + 1 == NSTAGE) ? 0 : slot + 1;
    }

    // ---- epilogue ----
    const int qr = lane >> 2;            // row within 8
    const int qc = (lane & 3) * 2;       // col pair within 8
    if (MODE == 0) {
#pragma unroll
        for (int am = 0; am < 4; am++)
#pragma unroll
            for (int hh = 0; hh < 2; hh++) {
                const int m = m0 + wm * 64 + am * 16 + qr + hh * 8;
                if (m >= cnt) continue;
                const size_t rowoff =
                    ((size_t)(e * MAXPE + m)) * H_ + n0 + wn * 32;
#pragma unroll
                for (int an = 0; an < 4; an++) {
                    const float* c = &acc[(am * 4 + an) * 4 + hh * 2];
                    float t0 = fmaxf(c[0], 0.f), t1 = fmaxf(c[1], 0.f);
                    float v0 = t0 * t0, v1 = t1 * t1;
                    uint32_t h, l;
                    split2(v0, v1, h, l);
                    const size_t off = rowoff + an * 8 + qc;
                    *(uint32_t*)(g_hhi + off) = h;
                    *(uint32_t*)(g_hlo + off) = l;
                }
            }
    } else {
#pragma unroll
        for (int am = 0; am < 4; am++)
#pragma unroll
            for (int hh = 0; hh < 2; hh++) {
                const int m = m0 + wm * 64 + am * 16 + qr + hh * 8;
                if (m >= cnt) continue;
                float* yrow = g_y + ((size_t)(part * E_ + e) * MAXPE + m) * D_ +
                              n0 + wn * 32;
#pragma unroll
                for (int an = 0; an < 4; an++) {
                    const float* c = &acc[(am * 4 + an) * 4 + hh * 2];
                    *(float2*)(yrow + an * 8 + qc) = make_float2(c[0], c[1]);
                }
            }
    }
}

// ---------------- combine: out[t] = w1*sum_p y[p][a1] + w2*sum_p y[p][a2] -------
__global__ __launch_bounds__(192) void combine_kernel(float* __restrict__ out) {
    const int t = blockIdx.x;
    const int i = threadIdx.x;  // 0..191 (D_/4 float4 columns)
    const int a1 = g_a1[t], a2 = g_a2[t];
    const float w1 = g_wt[a1], w2 = g_wt[a2];
    const float4* y4 = (const float4*)g_y;
    const size_t r1 = (size_t)a1 * (D_ / 4) + i;
    const size_t r2 = (size_t)a2 * (D_ / 4) + i;
    const size_t ps = (size_t)E_ * MAXPE * (D_ / 4);

    float4 s1 = y4[r1], s2 = y4[r2];
#pragma unroll
    for (int p = 1; p < SPLITK; p++) {
        float4 u = y4[p * ps + r1];
        s1.x += u.x; s1.y += u.y; s1.z += u.z; s1.w += u.w;
        float4 v = y4[p * ps + r2];
        s2.x += v.x; s2.y += v.y; s2.z += v.z; s2.w += v.w;
    }
    float4 o;
    o.x = w1 * s1.x + w2 * s2.x;
    o.y = w1 * s1.y + w2 * s2.y;
    o.z = w1 * s1.z + w2 * s2.z;
    o.w = w1 * s1.w + w2 * s2.w;
    ((float4*)out)[(size_t)t * (D_ / 4) + i] = o;
}

// ---------------- loss ----------------
__global__ void loss_kernel(float* __restrict__ out, int N, int out_size) {
    if (out_size <= N * D_) return;
    float loss = 0.0f;
    for (int e = 0; e < E_; e++)
        loss += (g_sumprob[e] / (float)N) * ((float)g_cnt[e] / (float)N);
    out[(size_t)N * D_] = loss * (float)E_;
}

// ---------------- launch ----------------
extern "C" void kernel_launch(void* const* d_in, const int* in_sizes, int n_in,
                              void* d_out, int out_size) {
    const float* x     = (const float*)d_in[0];
    const float* gw    = (const float*)d_in[1];
    const float* wfc   = (const float*)d_in[2];
    const float* wproj = (const float*)d_in[3];
    float* out = (float*)d_out;
    int N = in_sizes[0] / D_;  // 4096

    cudaFuncSetAttribute(moe_gemm_mma<0>, cudaFuncAttributeMaxDynamicSharedMemorySize,
                         SMEM_TOTAL);
    cudaFuncSetAttribute(moe_gemm_mma<1>, cudaFuncAttributeMaxDynamicSharedMemorySize,
                         SMEM_TOTAL);

    // resolve device-global plane addresses (host-side)
    u16 *xhi, *xlo, *wfchi, *wfclo, *wprohi, *wprolo, *hhi, *hlo;
    cudaGetSymbolAddress((void**)&xhi, g_xhi);
    cudaGetSymbolAddress((void**)&xlo, g_xlo);
    cudaGetSymbolAddress((void**)&wfchi, g_wfchi);
    cudaGetSymbolAddress((void**)&wfclo, g_wfclo);
    cudaGetSymbolAddress((void**)&wprohi, g_wprohi);
    cudaGetSymbolAddress((void**)&wprolo, g_wprolo);
    cudaGetSymbolAddress((void**)&hhi, g_hhi);
    cudaGetSymbolAddress((void**)&hlo, g_hlo);

    zero_kernel<<<64, 256>>>(out, out_size, N);
    cvt3_kernel<<<4096, 256>>>(x, wfc, wproj);
    gate_kernel<<<(N + 7) / 8, 256>>>(x, gw, N);
    reduce_probs_kernel<<<E_, 256>>>(N);

    // GEMM0: x = N-tiles fast-varying, y = M-tiles, z = expert
    dim3 g1(H_ / BN, MAXPE / BM, E_);
    moe_gemm_mma<0><<<g1, 256, SMEM_TOTAL>>>(xhi, xlo, wfchi, wfclo, D_);

    // GEMM1 split-K: z = expert * SPLITK + part
    dim3 g2(D_ / BN, MAXPE / BM, E_ * SPLITK);
    moe_gemm_mma<1><<<g2, 256, SMEM_TOTAL>>>(hhi, hlo, wprohi, wprolo, H_);

    combine_kernel<<<N, 192>>>(out);
    loss_kernel<<<1, 1>>>(out, N, out_size);
}

// round 17
// speedup vs baseline: 1.0200x; 1.0027x over previous
#include <cuda_runtime.h>
#include <cuda_bf16.h>
#include <cstdint>

// ---------------- problem constants ----------------
#define D_    768
#define H_    3072
#define E_    8
#define MAXPE 4096
#define NMAX  4096

#define BM 128
#define BN 128
#define BK 32

// fused GEMM segmentation
#define G0PE   ((H_ / BN) * (MAXPE / BM))   // 24*32 = 768 GEMM0 CTAs / expert
#define G1PE   ((D_ / BN) * (MAXPE / BM))   // 6*32  = 192 GEMM1 CTAs / expert
#define G0END  (E_ * G0PE)                  // 6144
#define G1END  (G0END + E_ * G1PE)          // 7680

typedef unsigned short u16;

// ---------------- device scratch (bf16 hi/lo planes) ----------------
__device__ u16   g_xhi[(size_t)NMAX * D_];
__device__ u16   g_xlo[(size_t)NMAX * D_];
__device__ u16   g_wfchi[(size_t)E_ * H_ * D_];
__device__ u16   g_wfclo[(size_t)E_ * H_ * D_];
__device__ u16   g_wprohi[(size_t)E_ * D_ * H_];
__device__ u16   g_wprolo[(size_t)E_ * D_ * H_];
__device__ u16   g_hhi[(size_t)E_ * MAXPE * H_];
__device__ u16   g_hlo[(size_t)E_ * MAXPE * H_];
__device__ int   g_tok[E_ * MAXPE];
__device__ float g_wt[E_ * MAXPE];
__device__ float g_probs[(size_t)NMAX * E_];
__device__ int   g_cnt[E_];
__device__ float g_sumprob[E_];
__device__ int   g_done0[E_];

// ---------------- helpers ----------------
__device__ __forceinline__ uint32_t smem_u32(const void* p) {
    uint32_t a;
    asm("{ .reg .u64 t; cvta.to.shared.u64 t, %1; cvt.u32.u64 %0, t; }" : "=r"(a) : "l"(p));
    return a;
}
__device__ __forceinline__ void ldsm4(uint32_t* r, uint32_t addr) {
    asm volatile("ldmatrix.sync.aligned.m8n8.x4.shared.b16 {%0,%1,%2,%3}, [%4];"
                 : "=r"(r[0]), "=r"(r[1]), "=r"(r[2]), "=r"(r[3]) : "r"(addr));
}
__device__ __forceinline__ void mma_bf16(float* c, const uint32_t* a, uint32_t b0, uint32_t b1) {
    asm volatile("mma.sync.aligned.m16n8k16.row.col.f32.bf16.bf16.f32 "
                 "{%0,%1,%2,%3}, {%4,%5,%6,%7}, {%8,%9}, {%0,%1,%2,%3};"
                 : "+f"(c[0]), "+f"(c[1]), "+f"(c[2]), "+f"(c[3])
                 : "r"(a[0]), "r"(a[1]), "r"(a[2]), "r"(a[3]), "r"(b0), "r"(b1));
}
__device__ __forceinline__ void cpa16(uint32_t dst, const void* src) {
    asm volatile("cp.async.cg.shared.global [%0], [%1], 16;" :: "r"(dst), "l"(src));
}
__device__ __forceinline__ void cp_commit() {
    asm volatile("cp.async.commit_group;" ::: "memory");
}
__device__ __forceinline__ void cp_wait1() {
    asm volatile("cp.async.wait_group 1;" ::: "memory");
}
// split two floats -> hi bf16x2 (packed) and lo bf16x2 (packed)
__device__ __forceinline__ void split2(float x, float y, uint32_t& h, uint32_t& l) {
    __nv_bfloat162 a = __floats2bfloat162_rn(x, y);
    h = *reinterpret_cast<uint32_t*>(&a);
    float f0 = __uint_as_float(h << 16);
    float f1 = __uint_as_float(h & 0xffff0000u);
    __nv_bfloat162 b = __floats2bfloat162_rn(x - f0, y - f1);
    l = *reinterpret_cast<uint32_t*>(&b);
}

// ---------------- dependency counters ----------------
__device__ __forceinline__ void signal_cnt(int* p) {
    __syncthreads();
    __threadfence();
    if (threadIdx.x == 0) atomicAdd(p, 1);
}
__device__ __forceinline__ void wait_cnt(int* p, int target) {
    if (threadIdx.x == 0) {
        while (atomicAdd(p, 0) < target) __nanosleep(64);
    }
    __syncthreads();
    __threadfence();
}

// ---------------- kernel: fused fp32 -> bf16 hi/lo planes (x, wfc, wproj) ------
#define X4  (NMAX * D_ / 4)
#define W4  (E_ * H_ * D_ / 4)
__global__ void cvt3_kernel(const float* __restrict__ x, const float* __restrict__ wfc,
                            const float* __restrict__ wproj) {
    const int total = X4 + 2 * W4;
    for (int i = blockIdx.x * blockDim.x + threadIdx.x; i < total;
         i += gridDim.x * blockDim.x) {
        const float4* src;
        uint2 *hi, *lo;
        int j;
        if (i < X4) {
            j = i; src = (const float4*)x;
            hi = (uint2*)g_xhi; lo = (uint2*)g_xlo;
        } else if (i < X4 + W4) {
            j = i - X4; src = (const float4*)wfc;
            hi = (uint2*)g_wfchi; lo = (uint2*)g_wfclo;
        } else {
            j = i - X4 - W4; src = (const float4*)wproj;
            hi = (uint2*)g_wprohi; lo = (uint2*)g_wprolo;
        }
        float4 v = src[j];
        uint32_t h0, h1, l0, l1;
        split2(v.x, v.y, h0, l0);
        split2(v.z, v.w, h1, l1);
        hi[j] = make_uint2(h0, h1);
        lo[j] = make_uint2(l0, l1);
    }
}

// ---------------- kernel 0: zero output + counters ----------------
__global__ void zero_kernel(float* __restrict__ out, int out_size) {
    for (int i = blockIdx.x * blockDim.x + threadIdx.x; i < out_size;
         i += gridDim.x * blockDim.x)
        out[i] = 0.0f;
    if (blockIdx.x == 0 && threadIdx.x < E_) {
        g_cnt[threadIdx.x]   = 0;
        g_done0[threadIdx.x] = 0;
    }
}

// ---------------- kernel 1: gating ----------------
__global__ __launch_bounds__(256) void gate_kernel(const float* __restrict__ x,
                                                   const float* __restrict__ gw,
                                                   int N) {
    int token = blockIdx.x * 8 + (threadIdx.x >> 5);
    int lane  = threadIdx.x & 31;
    if (token >= N) return;

    const float* xr = x + (size_t)token * D_;
    float xs[D_ / 32];
#pragma unroll
    for (int i = 0; i < D_ / 32; i++) xs[i] = xr[lane + i * 32];

    float p[E_];
#pragma unroll
    for (int e = 0; e < E_; e++) {
        const float* g = gw + e * D_;
        float s = 0.0f;
#pragma unroll
        for (int i = 0; i < D_ / 32; i++) s += xs[i] * g[lane + i * 32];
#pragma unroll
        for (int o = 16; o; o >>= 1) s += __shfl_xor_sync(0xffffffffu, s, o);
        p[e] = s;
    }

    if (lane == 0) {
        float mx = p[0];
#pragma unroll
        for (int e = 1; e < E_; e++) mx = fmaxf(mx, p[e]);
        float sum = 0.0f;
#pragma unroll
        for (int e = 0; e < E_; e++) { p[e] = expf(p[e] - mx); sum += p[e]; }
        float inv = 1.0f / sum;
#pragma unroll
        for (int e = 0; e < E_; e++) {
            p[e] *= inv;
            g_probs[(size_t)token * E_ + e] = p[e];
        }
        int i1 = 0;
#pragma unroll
        for (int e = 1; e < E_; e++) if (p[e] > p[i1]) i1 = e;
        int i2 = (i1 == 0) ? 1 : 0;
#pragma unroll
        for (int e = 0; e < E_; e++) if (e != i1 && p[e] > p[i2]) i2 = e;
        float s2 = p[i1] + p[i2];
        float w1 = p[i1] / s2, w2 = p[i2] / s2;

        int pos = atomicAdd(&g_cnt[i1], 1);
        g_tok[i1 * MAXPE + pos] = token; g_wt[i1 * MAXPE + pos] = w1;
        pos = atomicAdd(&g_cnt[i2], 1);
        g_tok[i2 * MAXPE + pos] = token; g_wt[i2 * MAXPE + pos] = w2;
    }
}

// ---------------- kernel 2: deterministic column-sum of probs ----------------
__global__ void reduce_probs_kernel(int N) {
    __shared__ float sm[256];
    int e = blockIdx.x;
    float s = 0.0f;
    for (int i = threadIdx.x; i < N; i += 256) s += g_probs[(size_t)i * E_ + e];
    sm[threadIdx.x] = s;
    __syncthreads();
    for (int o = 128; o; o >>= 1) {
        if (threadIdx.x < o) sm[threadIdx.x] += sm[threadIdx.x + o];
        __syncthreads();
    }
    if (threadIdx.x == 0) g_sumprob[e] = sm[0];
}

// ---------------- GEMM body: mma.sync bf16x3, cp.async 3-stage ----------------
// Block tile 128x128x32; warp grid 2x4, warp tile 64x32; 64 accumulators.
// Stage (32KB): A_hi[128 rows x 64B] @0, A_lo @8192, B_hi @16384, B_lo @24576.
// Chunk c of row r stored at 16B slot (c ^ ((r>>1)&3)) -> conflict-free.
// MODE 0: h = relu(x_planes @ wfc_planes^T)^2 -> g_h hi/lo planes (Kdim = D_)
// MODE 1: out += wt * (g_h planes @ wproj planes^T)  (atomicAdd) (Kdim = H_)
#define STAGE_BYTES 32768u
#define NSTAGE      3
#define SMEM_TOTAL  (NSTAGE * STAGE_BYTES)

template <int MODE>
__device__ __forceinline__ void gemm_body(const u16* __restrict__ Ahi,
                                          const u16* __restrict__ Alo,
                                          const u16* __restrict__ Bhi,
                                          const u16* __restrict__ Blo,
                                          float* __restrict__ out, int Kdim, int e,
                                          int m0, int n0, int cnt, uint32_t sb) {
    const int tid  = threadIdx.x;
    const int warp = tid >> 5, lane = tid & 31;
    const int wm = warp >> 2, wn = warp & 3;  // 2 x 4 warp grid, warp tile 64x32

    // ---- loader mapping: 2 threads per row, 2 chunks of 16B each plane ----
    const int lrow  = tid >> 1;
    const int lhalf = tid & 1;
    const u16 *a_hi, *a_lo;
    if (MODE == 0) {
        int m   = m0 + lrow;
        int tok = g_tok[e * MAXPE + ((m < cnt) ? m : m0)];
        a_hi = Ahi + (size_t)tok * D_ + lhalf * 16;
        a_lo = Alo + (size_t)tok * D_ + lhalf * 16;
    } else {
        size_t off = ((size_t)(e * MAXPE + m0 + lrow)) * H_ + lhalf * 16;
        a_hi = Ahi + off;
        a_lo = Alo + off;
    }
    const size_t boff = (size_t)e * ((size_t)H_ * D_) + (size_t)(n0 + lrow) * Kdim +
                        (size_t)(lhalf * 16);
    const u16* b_hi = Bhi + boff;
    const u16* b_lo = Blo + boff;

    // swizzled dst offsets for the 2 chunks (c = lhalf*2, lhalf*2+1)
    const uint32_t lsw   = (uint32_t)((lrow >> 1) & 3);
    const uint32_t st_c0 = (uint32_t)lrow * 64u + (((uint32_t)(lhalf * 2) ^ lsw) * 16u);
    const uint32_t st_c1 = (uint32_t)lrow * 64u + (((uint32_t)(lhalf * 2 + 1) ^ lsw) * 16u);

    // ---- ldmatrix per-lane swizzled addressing ----
    const int      row_a = wm * 64 + (lane & 15);
    const uint32_t sw_a  = (uint32_t)((row_a >> 1) & 3);
    const uint32_t a_row = (uint32_t)row_a * 64u;
    const uint32_t ca    = (uint32_t)(lane >> 4);
    const int      row_b = wn * 32 + ((lane >> 4) & 1) * 8 + (lane & 7);
    const uint32_t sw_b  = (uint32_t)((row_b >> 1) & 3);
    const uint32_t b_row = (uint32_t)row_b * 64u;
    const uint32_t cb    = (uint32_t)((lane >> 3) & 1);

    float acc[64];
#pragma unroll
    for (int i = 0; i < 64; i++) acc[i] = 0.0f;

    const int nk = Kdim / BK;

    // stage loader: 8 x cp.async(16B) per thread
    auto load_stage = [&](int kt, int slot) {
        const uint32_t base = sb + (uint32_t)slot * STAGE_BYTES;
        const int koff = kt * BK;
        cpa16(base + st_c0, a_hi + koff);
        cpa16(base + st_c1, a_hi + koff + 8);
        cpa16(base + 8192 + st_c0, a_lo + koff);
        cpa16(base + 8192 + st_c1, a_lo + koff + 8);
        cpa16(base + 16384 + st_c0, b_hi + koff);
        cpa16(base + 16384 + st_c1, b_hi + koff + 8);
        cpa16(base + 24576 + st_c0, b_lo + koff);
        cpa16(base + 24576 + st_c1, b_lo + koff + 8);
    };

    // prologue: fill stages 0 and 1
    load_stage(0, 0);
    cp_commit();
    if (nk > 1) load_stage(1, 1);
    cp_commit();

    int slot = 0;
    for (int kt = 0; kt < nk; ++kt) {
        cp_wait1();
        __syncthreads();
        if (kt + 2 < nk) {
            int s2 = slot + 2;
            if (s2 >= NSTAGE) s2 -= NSTAGE;
            load_stage(kt + 2, s2);
        }
        cp_commit();

        const uint32_t base = sb + (uint32_t)slot * STAGE_BYTES;
#pragma unroll
        for (int ks = 0; ks < 2; ks++) {
            uint32_t ah[4][4], al[4][4];
            const uint32_t aoff = base + a_row + ((((uint32_t)(ks * 2) + ca) ^ sw_a) * 16u);
            const uint32_t boff2 =
                base + 16384 + b_row + ((((uint32_t)(ks * 2) + cb) ^ sw_b) * 16u);
#pragma unroll
            for (int am = 0; am < 4; am++) {
                ldsm4(ah[am], aoff + am * 1024);
                ldsm4(al[am], aoff + 8192 + am * 1024);
            }
#pragma unroll
            for (int g = 0; g < 2; g++) {
                uint32_t bh[4], bl[4];
                ldsm4(bh, boff2 + g * 1024);
                ldsm4(bl, boff2 + 8192 + g * 1024);
#pragma unroll
                for (int am = 0; am < 4; am++) {
                    float* c0 = &acc[(am * 4 + g * 2) * 4];
                    float* c1 = &acc[(am * 4 + g * 2 + 1) * 4];
                    mma_bf16(c0, ah[am], bh[0], bh[1]);
                    mma_bf16(c1, ah[am], bh[2], bh[3]);
                    mma_bf16(c0, ah[am], bl[0], bl[1]);
                    mma_bf16(c1, ah[am], bl[2], bl[3]);
                    mma_bf16(c0, al[am], bh[0], bh[1]);
                    mma_bf16(c1, al[am], bh[2], bh[3]);
                }
            }
        }
        slot = (slot + 1 == NSTAGE) ? 0 : slot + 1;
    }

    // ---- epilogue ----
    const int qr = lane >> 2;            // row within 8
    const int qc = (lane & 3) * 2;       // col pair within 8
    if (MODE == 0) {
#pragma unroll
        for (int am = 0; am < 4; am++)
#pragma unroll
            for (int hh = 0; hh < 2; hh++) {
                const int m = m0 + wm * 64 + am * 16 + qr + hh * 8;
                if (m >= cnt) continue;
                const size_t rowoff =
                    ((size_t)(e * MAXPE + m)) * H_ + n0 + wn * 32;
#pragma unroll
                for (int an = 0; an < 4; an++) {
                    const float* c = &acc[(am * 4 + an) * 4 + hh * 2];
                    float t0 = fmaxf(c[0], 0.f), t1 = fmaxf(c[1], 0.f);
                    float v0 = t0 * t0, v1 = t1 * t1;
                    uint32_t h, l;
                    split2(v0, v1, h, l);
                    const size_t off = rowoff + an * 8 + qc;
                    *(uint32_t*)(g_hhi + off) = h;
                    *(uint32_t*)(g_hlo + off) = l;
                }
            }
    } else {
#pragma unroll
        for (int am = 0; am < 4; am++)
#pragma unroll
            for (int hh = 0; hh < 2; hh++) {
                const int m = m0 + wm * 64 + am * 16 + qr + hh * 8;
                if (m >= cnt) continue;
                const int tok = g_tok[e * MAXPE + m];
                const float wt = g_wt[e * MAXPE + m];
                float* orow = out + (size_t)tok * D_ + n0 + wn * 32;
#pragma unroll
                for (int an = 0; an < 4; an++) {
                    const float* c = &acc[(am * 4 + an) * 4 + hh * 2];
                    atomicAdd(orow + an * 8 + qc, wt * c[0]);
                    atomicAdd(orow + an * 8 + qc + 1, wt * c[1]);
                }
            }
    }
}

// ---------------- fused GEMM kernel: GEMM0 blocks then GEMM1 blocks ------------
// Single forward dependency: GEMM1(e) spins on g_done0[e]==G0PE. GEMM0 never
// waits. Inactive GEMM1 blocks exit BEFORE waiting. GEMM1 blocks are dispatched
// only after all GEMM0 blocks -> they can only occupy otherwise-idle tail slots.
__global__ __launch_bounds__(256, 2) void moe_fused_gemm(
    const u16* __restrict__ xhi, const u16* __restrict__ xlo,
    const u16* __restrict__ wfchi, const u16* __restrict__ wfclo,
    const u16* __restrict__ wprohi, const u16* __restrict__ wprolo,
    const u16* __restrict__ hhi, const u16* __restrict__ hlo,
    float* __restrict__ out) {
    extern __shared__ __align__(128) char smem[];
    const uint32_t sb  = smem_u32(smem);
    const int      bid = blockIdx.x;

    if (bid < G0END) {
        const int e  = bid / G0PE, t = bid % G0PE;
        const int nt = t % (H_ / BN), mt = t / (H_ / BN);
        const int cnt = g_cnt[e];
        const int m0  = mt * BM;
        if (m0 < cnt)
            gemm_body<0>(xhi, xlo, wfchi, wfclo, nullptr, D_, e, m0, nt * BN, cnt, sb);
        signal_cnt(&g_done0[e]);
    } else {
        const int idx = bid - G0END;
        const int e   = idx / G1PE, t = idx % G1PE;
        const int nt  = t % (D_ / BN), mt = t / (D_ / BN);
        const int cnt = g_cnt[e];
        const int m0  = mt * BM;
        if (m0 >= cnt) return;        // exit before waiting
        wait_cnt(&g_done0[e], G0PE);
        gemm_body<1>(hhi, hlo, wprohi, wprolo, out, H_, e, m0, nt * BN, cnt, sb);
    }
}

// ---------------- loss ----------------
__global__ void loss_kernel(float* __restrict__ out, int N, int out_size) {
    if (out_size <= N * D_) return;
    float loss = 0.0f;
    for (int e = 0; e < E_; e++)
        loss += (g_sumprob[e] / (float)N) * ((float)g_cnt[e] / (float)N);
    out[(size_t)N * D_] = loss * (float)E_;
}

// ---------------- launch ----------------
extern "C" void kernel_launch(void* const* d_in, const int* in_sizes, int n_in,
                              void* d_out, int out_size) {
    const float* x     = (const float*)d_in[0];
    const float* gw    = (const float*)d_in[1];
    const float* wfc   = (const float*)d_in[2];
    const float* wproj = (const float*)d_in[3];
    float* out = (float*)d_out;
    int N = in_sizes[0] / D_;  // 4096

    cudaFuncSetAttribute(moe_fused_gemm, cudaFuncAttributeMaxDynamicSharedMemorySize,
                         SMEM_TOTAL);

    // resolve device-global plane addresses (host-side)
    u16 *xhi, *xlo, *wfchi, *wfclo, *wprohi, *wprolo, *hhi, *hlo;
    cudaGetSymbolAddress((void**)&xhi, g_xhi);
    cudaGetSymbolAddress((void**)&xlo, g_xlo);
    cudaGetSymbolAddress((void**)&wfchi, g_wfchi);
    cudaGetSymbolAddress((void**)&wfclo, g_wfclo);
    cudaGetSymbolAddress((void**)&wprohi, g_wprohi);
    cudaGetSymbolAddress((void**)&wprolo, g_wprolo);
    cudaGetSymbolAddress((void**)&hhi, g_hhi);
    cudaGetSymbolAddress((void**)&hlo, g_hlo);

    zero_kernel<<<1024, 256>>>(out, out_size);
    cvt3_kernel<<<4096, 256>>>(x, wfc, wproj);
    gate_kernel<<<(N + 7) / 8, 256>>>(x, gw, N);
    reduce_probs_kernel<<<E_, 256>>>(N);

    moe_fused_gemm<<<G1END, 256, SMEM_TOTAL>>>(xhi, xlo, wfchi, wfclo,
                                               wprohi, wprolo, hhi, hlo, out);

    loss_kernel<<<1, 1>>>(out, N, out_size);
}